// round 12
// baseline (speedup 1.0000x reference)
#include <cuda_runtime.h>
#include <cuda_fp16.h>
#include <math.h>
#include <stdint.h>

// ---------------- problem constants ----------------
#define Bb 16
#define Ls 511
#define Ss 512
#define Dd 1024
#define HIDh 512
#define DFFf 2048
#define EAe 256
#define NHh 4
#define HDh 256   // D/NH

// ---------------- GEMM tile config: CTA 128x128, 4 warps (2x2) of 64x64, BK=64, 3 stages
#define BKk 64
#define AP 72                     // A smem pitch (halves)
#define BP1 72                    // B smem pitch, TB=1
#define BP0 136                   // B smem pitch, TB=0 (128 + 8 pad)
#define AE_H (128*AP)             // 9216 halves per A stage
#define STG1_H (AE_H + 128*BP1)   // 18432
#define STG0_H (AE_H + 64*BP0)    // 17920
#define SMEM_TB1 (STG1_H*2*3)     // 110592 B
#define SMEM_TB0 (STG0_H*2*3)     // 107520 B

// ---------------- scratch (static device memory) ----------------
__device__ float  d_h   [8192L*1024];
__device__ float  d_x2  [8192L*1024];
__device__ __half d_h16 [8192L*1024];
__device__ __half d_mem16[8192L*1024];
__device__ __half d_qkv16[8192L*3072];
__device__ __half d_att16[64L*512*512];
__device__ __half d_xh  [8192L*2048];
__device__ __half d_wh  [38535168];

// weight-region offsets in d_wh (halves) — contiguous pack
#define W_SAQKV  0L
#define W_SAOUT  9437184L
#define W_CAQKV  12582912L
#define W_CAOUT  22020096L
#define W_FFW1   25165824L
#define W_FFW2   31457280L
#define W_INPW2  37748736L
#define W_PROJW1 38010880L

// ---------------- asm helpers ----------------
__device__ __forceinline__ void cpa(uint32_t d, const __half* s) {
    asm volatile("cp.async.cg.shared.global [%0], [%1], 16;" :: "r"(d), "l"(s));
}
#define LDSM4(r0,r1,r2,r3,a) \
    asm volatile("ldmatrix.sync.aligned.m8n8.x4.shared.b16 {%0,%1,%2,%3}, [%4];" \
                 : "=r"(r0),"=r"(r1),"=r"(r2),"=r"(r3) : "r"(a))
#define LDSM4T(r0,r1,r2,r3,a) \
    asm volatile("ldmatrix.sync.aligned.m8n8.x4.trans.shared.b16 {%0,%1,%2,%3}, [%4];" \
                 : "=r"(r0),"=r"(r1),"=r"(r2),"=r"(r3) : "r"(a))

__device__ __forceinline__ void mma16(float* c, const uint32_t* a, const uint32_t* b) {
    asm volatile(
        "mma.sync.aligned.m16n8k16.row.col.f32.f16.f16.f32 "
        "{%0,%1,%2,%3}, {%4,%5,%6,%7}, {%8,%9}, {%0,%1,%2,%3};"
        : "+f"(c[0]), "+f"(c[1]), "+f"(c[2]), "+f"(c[3])
        : "r"(a[0]), "r"(a[1]), "r"(a[2]), "r"(a[3]), "r"(b[0]), "r"(b[1]));
}

// ---------------- fp16 tensor-core GEMM ----------------
// C = act(alpha * A @ op(B) + bias).  A [M,K] half row-major.
// TB=1: B [N,K]; TB=0: B [K,N]. OUTH=1: C half, else C float.
// CTA 128x128, 4 warps (2x2) of 64x64, BK=64, 3-stage cp.async, 2 CTAs/SM.
// cmode: 0 = dense; 1 = causal score GEMM (skip CTA tiles with n0>m0);
//        2 = causal P@V GEMM (K-loop truncated at m0+128; P upper triangle is zero).
template<int TB, int ACT, int OUTH>
__global__ void __launch_bounds__(128, 2)
mma_gemm_k(const __half* __restrict__ A, const __half* __restrict__ B,
           const float* __restrict__ bias, void* __restrict__ Cv,
           int K, int lda, int ldb, int ldc,
           long sAb, long sAh, long sBb, long sBh, long sCb, long sCh,
           int nh, float alpha, int cmode)
{
    constexpr int BP = TB ? BP1 : BP0;
    constexpr int STG_H = TB ? STG1_H : STG0_H;
    constexpr uint32_t STG_B = STG_H * 2;
    constexpr uint32_t AE_B = AE_H * 2;

    int m0 = blockIdx.y * 128, n0 = blockIdx.x * 128;
    if (cmode == 1 && n0 > m0) return;   // upper-triangle tile: P is zero there

    extern __shared__ __half smem[];
    uint32_t sb = (uint32_t)__cvta_generic_to_shared(smem);

    int tid = threadIdx.x;
    int wid = tid >> 5, lane = tid & 31;
    int gq = lane >> 2, gr = lane & 3;
    int wm0 = (wid >> 1) * 64;     // 2 warp rows
    int wn0 = (wid & 1) * 64;      // 2 warp cols

    int z = blockIdx.z, bb = z / nh, hh = z - bb * nh;
    A += bb * sAb + hh * sAh;
    B += bb * sBb + hh * sBh;

    float acc[4][8][4];
    #pragma unroll
    for (int i = 0; i < 4; i++)
        #pragma unroll
        for (int j = 0; j < 8; j++)
            #pragma unroll
            for (int q = 0; q < 4; q++) acc[i][j][q] = 0.f;

    auto ldst = [&](int s, int k0) {
        uint32_t base = sb + s * STG_B;
        // A: 128 rows x 64 halves = 1024 16B-chunks, 128 threads -> 8 each
        #pragma unroll
        for (int i = 0; i < 8; i++) {
            int ch = tid + 128 * i;
            int row = ch & 127, c = ch >> 7;
            cpa(base + (uint32_t)(row * AP + c * 8) * 2,
                A + (long)(m0 + row) * lda + k0 + c * 8);
        }
        uint32_t bbase = base + AE_B;
        if (TB) {
            #pragma unroll
            for (int i = 0; i < 8; i++) {
                int ch = tid + 128 * i;
                int row = ch & 127, c = ch >> 7;
                cpa(bbase + (uint32_t)(row * BP + c * 8) * 2,
                    B + (long)(n0 + row) * ldb + k0 + c * 8);
            }
        } else {
            // B: 64 k-rows x 128 halves = 1024 chunks
            #pragma unroll
            for (int i = 0; i < 8; i++) {
                int ch = tid + 128 * i;
                int row = ch >> 4, c = ch & 15;
                cpa(bbase + (uint32_t)(row * BP + c * 8) * 2,
                    B + (long)(k0 + row) * ldb + n0 + c * 8);
            }
        }
        asm volatile("cp.async.commit_group;" ::: "memory");
    };

    int nk = K / BKk;
    if (cmode == 2) { int lim = (m0 >> 6) + 2; if (lim < nk) nk = lim; }

    ldst(0, 0); ldst(1, BKk);

    uint32_t a_lo = (uint32_t)((lane & 15) * AP + (lane >> 4) * 8) * 2;
    uint32_t b_lo = (uint32_t)((lane & 15) * BP + (lane >> 4) * 8) * 2;

    for (int it = 0; it < nk; it++) {
        asm volatile("cp.async.wait_group 1;" ::: "memory");
        __syncthreads();
        if (it + 2 < nk) ldst((it + 2) % 3, (it + 2) * BKk);
        else asm volatile("cp.async.commit_group;" ::: "memory");

        uint32_t sbase = sb + (uint32_t)(it % 3) * STG_B;
        uint32_t aA = sbase + a_lo;
        uint32_t aB = sbase + AE_B + b_lo;

        #pragma unroll
        for (int kk = 0; kk < 4; kk++) {
            uint32_t afr[4][4];
            #pragma unroll
            for (int mi = 0; mi < 4; mi++)
                LDSM4(afr[mi][0], afr[mi][1], afr[mi][2], afr[mi][3],
                      aA + (uint32_t)((wm0 + mi * 16) * AP) * 2 + kk * 32);
            uint32_t bfr[8][2];
            #pragma unroll
            for (int nj = 0; nj < 4; nj++) {
                uint32_t r0, r1, r2, r3;
                if (TB) {
                    LDSM4(r0, r1, r2, r3,
                          aB + (uint32_t)((wn0 + nj * 16) * BP) * 2 + kk * 32);
                    bfr[2*nj][0] = r0; bfr[2*nj][1] = r2;
                    bfr[2*nj+1][0] = r1; bfr[2*nj+1][1] = r3;
                } else {
                    LDSM4T(r0, r1, r2, r3,
                           aB + (uint32_t)(kk * 16 * BP) * 2 + (uint32_t)(wn0 + nj * 16) * 2);
                    bfr[2*nj][0] = r0; bfr[2*nj][1] = r1;
                    bfr[2*nj+1][0] = r2; bfr[2*nj+1][1] = r3;
                }
            }
            #pragma unroll
            for (int mi = 0; mi < 4; mi++)
                #pragma unroll
                for (int ni = 0; ni < 8; ni++)
                    mma16(acc[mi][ni], afr[mi], bfr[ni]);
        }
    }

    // epilogue
    #pragma unroll
    for (int mi = 0; mi < 4; mi++) {
        int r0 = m0 + wm0 + mi * 16 + gq;
        #pragma unroll
        for (int ni = 0; ni < 8; ni++) {
            int c0 = n0 + wn0 + ni * 8 + gr * 2;
            float bz0 = 0.f, bz1 = 0.f;
            if (bias) { bz0 = bias[c0]; bz1 = bias[c0 + 1]; }
            #pragma unroll
            for (int hi = 0; hi < 2; hi++) {
                float x = acc[mi][ni][hi * 2 + 0] * alpha + bz0;
                float y = acc[mi][ni][hi * 2 + 1] * alpha + bz1;
                if (ACT == 1) { x = fmaxf(x, 0.f); y = fmaxf(y, 0.f); }
                if (ACT == 2) { x = (x >= 0.f) ? x : 0.01f * x; y = (y >= 0.f) ? y : 0.01f * y; }
                long off = (long)(r0 + hi * 8) * ldc + c0 + bb * sCb + hh * sCh;
                if (OUTH) {
                    *reinterpret_cast<__half2*>((__half*)Cv + off) = __floats2half2_rn(x, y);
                } else {
                    float2 v; v.x = x; v.y = y;
                    *reinterpret_cast<float2*>((float*)Cv + off) = v;
                }
            }
        }
    }
}

// ---------------- fused weight convert: 4 fp32 segments -> contiguous fp16 pack ----
__global__ void cvtg_k(const float* __restrict__ s0, const float* __restrict__ s1,
                       const float* __restrict__ s2, const float* __restrict__ s3,
                       __half* __restrict__ dst, long c0, long c1, long c2, long c3)
{
    long i = (long)blockIdx.x * 256 + threadIdx.x;
    if (i >= c3) return;
    const float* s;
    long base;
    if (i < c0)      { s = s0; base = 0; }
    else if (i < c1) { s = s1; base = c0; }
    else if (i < c2) { s = s2; base = c1; }
    else             { s = s3; base = c2; }
    float4 v = reinterpret_cast<const float4*>(s)[i - base];
    __half2* o = reinterpret_cast<__half2*>(dst + i * 4);
    o[0] = __floats2half2_rn(v.x, v.y);
    o[1] = __floats2half2_rn(v.z, v.w);
}

// ---------------- softmax: fp16 in-place (scores -> probabilities) ----------------
__global__ void softmax_k(__half* __restrict__ att, int causal)
{
    int q = blockIdx.x;
    int z = blockIdx.y;
    __half* p = att + ((long)z * Ss + q) * Ss;
    int len = causal ? (q + 1) : Ss;
    int tid = threadIdx.x;
    __shared__ float sh[8];

    float v0 = (tid < len) ? __half2float(p[tid]) : -1e30f;
    float v1 = (tid + 256 < len) ? __half2float(p[tid + 256]) : -1e30f;
    float mx = fmaxf(v0, v1);
    #pragma unroll
    for (int o2 = 16; o2; o2 >>= 1) mx = fmaxf(mx, __shfl_xor_sync(~0u, mx, o2));
    if ((tid & 31) == 0) sh[tid >> 5] = mx;
    __syncthreads();
    mx = sh[0];
    #pragma unroll
    for (int w = 1; w < 8; w++) mx = fmaxf(mx, sh[w]);

    float e0 = (tid < len) ? __expf(v0 - mx) : 0.f;
    float e1 = (tid + 256 < len) ? __expf(v1 - mx) : 0.f;
    float s = e0 + e1;
    #pragma unroll
    for (int o2 = 16; o2; o2 >>= 1) s += __shfl_xor_sync(~0u, s, o2);
    __syncthreads();
    if ((tid & 31) == 0) sh[tid >> 5] = s;
    __syncthreads();
    s = 0.f;
    #pragma unroll
    for (int w = 0; w < 8; w++) s += sh[w];
    float inv = 1.f / s;

    p[tid]       = __float2half_rn(e0 * inv);
    p[tid + 256] = __float2half_rn(e1 * inv);
}

// ---------------- h = LN(h + delta); also write h16 ----------------
__global__ void ln_add_k(float* __restrict__ h, __half* __restrict__ h16,
                         const float* __restrict__ d,
                         const float* __restrict__ w, const float* __restrict__ b)
{
    long row = blockIdx.x;
    float* x = h + row * Dd;
    __half* x16 = h16 + row * Dd;
    const float* dd = d + row * Dd;
    int tid = threadIdx.x;
    __shared__ float sh[256];

    float v[4];
    float s = 0.f;
    #pragma unroll
    for (int t = 0; t < 4; t++) { int i = tid + t * 256; v[t] = x[i] + dd[i]; s += v[t]; }
    sh[tid] = s; __syncthreads();
    for (int st = 128; st > 0; st >>= 1) { if (tid < st) sh[tid] += sh[tid + st]; __syncthreads(); }
    float mean = sh[0] * (1.f / Dd); __syncthreads();

    float s2 = 0.f;
    #pragma unroll
    for (int t = 0; t < 4; t++) { float u = v[t] - mean; s2 += u * u; }
    sh[tid] = s2; __syncthreads();
    for (int st = 128; st > 0; st >>= 1) { if (tid < st) sh[tid] += sh[tid + st]; __syncthreads(); }
    float rstd = rsqrtf(sh[0] * (1.f / Dd) + 1e-5f);

    #pragma unroll
    for (int t = 0; t < 4; t++) {
        int i = tid + t * 256;
        float r = (v[t] - mean) * rstd * w[i] + b[i];
        x[i] = r;
        x16[i] = __float2half_rn(r);
    }
}

// ---------------- input projection stage 1 (half out) ----------------
__global__ void build1_k(const float* __restrict__ tgtn, const float* __restrict__ bos,
                         const float* __restrict__ w1, const float* __restrict__ b1,
                         __half* __restrict__ out)
{
    long idx = (long)blockIdx.x * 256 + threadIdx.x;
    long row = idx >> 9;
    int j = (int)(idx & 511);
    int bb = (int)(row >> 9);
    int s = (int)(row & 511);
    float t = (s == 0) ? bos[0] : tgtn[bb * Ls + s - 1];
    float v = t * w1[j] + b1[j];
    out[idx] = __float2half_rn((v >= 0.f) ? v : 0.01f * v);
}

// ---------------- assemble tgt(+PE) -> h,h16 and mem16 ----------------
__global__ void build2_k(const float* __restrict__ x2, const float* __restrict__ gs,
                         const float* __restrict__ prev, const float* __restrict__ cur,
                         float* __restrict__ h, __half* __restrict__ h16,
                         __half* __restrict__ mem16)
{
    int row = blockIdx.x;
    int bb = row >> 9;
    int s = row & 511;
    long ob = (long)row * Dd;
    for (int i = threadIdx.x; i < Dd; i += 256) {
        float tv, mv;
        if (i < HIDh) {
            int jj = i & ~1;
            float div = __expf((float)jj * (-9.210340371976184f / 512.f));
            double ang = (double)s * (double)div;
            double r = ang - 6.283185307179586 * rint(ang * 0.15915494309189535);
            float fr = (float)r;
            float pe = (i & 1) ? cosf(fr) : sinf(fr);
            tv = x2[(long)row * HIDh + i] + pe;
            mv = gs[(long)row * HIDh + i];
        } else if (i < HIDh + EAe) {
            float a = prev[bb * EAe + (i - HIDh)];
            tv = a; mv = a;
        } else {
            float a = cur[bb * EAe + (i - HIDh - EAe)];
            tv = a; mv = a;
        }
        h[ob + i] = tv;
        h16[ob + i] = __float2half_rn(tv);
        mem16[ob + i] = __float2half_rn(mv);
    }
}

// ---------------- final: y2 = y1 @ w2^T + b2, masked ----------------
__global__ void final_k(const float* __restrict__ y1, const float* __restrict__ w2,
                        const float* __restrict__ b2, const int* __restrict__ basis,
                        float* __restrict__ out)
{
    int idx = blockIdx.x * 8 + (threadIdx.x >> 5);
    if (idx >= Bb * Ls) return;
    int bb = idx / Ls, l = idx % Ls;
    const float* r = y1 + ((long)bb * Ss + l + 1) * HIDh;
    int lane = threadIdx.x & 31;
    float s = 0.f;
    for (int j = lane; j < HIDh; j += 32) s += r[j] * w2[j];
    #pragma unroll
    for (int o = 16; o; o >>= 1) s += __shfl_xor_sync(0xffffffffu, s, o);
    if (lane == 0) out[idx] = (l < basis[bb]) ? (s + b2[0]) : 0.f;
}

// ---------------- host-side launcher ----------------
static void hgemm(int TB, int ACT, int OUTH,
                  const __half* A, const __half* B, const float* bias, void* C,
                  int M, int N, int K, int lda, int ldb, int ldc,
                  long sAb, long sAh, long sBb, long sBh, long sCb, long sCh,
                  int nb, int nh, float alpha, int cmode)
{
    dim3 grid(N / 128, M / 128, nb * nh);
#define HCALL(tb, act, oh, sm) mma_gemm_k<tb, act, oh><<<grid, 128, sm>>>( \
        A, B, bias, C, K, lda, ldb, ldc, sAb, sAh, sBb, sBh, sCb, sCh, nh, alpha, cmode)
    if (TB == 1 && ACT == 0 && OUTH == 1) HCALL(1, 0, 1, SMEM_TB1);
    else if (TB == 1 && ACT == 0 && OUTH == 0) HCALL(1, 0, 0, SMEM_TB1);
    else if (TB == 1 && ACT == 1 && OUTH == 1) HCALL(1, 1, 1, SMEM_TB1);
    else if (TB == 1 && ACT == 2 && OUTH == 0) HCALL(1, 2, 0, SMEM_TB1);
    else HCALL(0, 0, 1, SMEM_TB0);
#undef HCALL
}

extern "C" void kernel_launch(void* const* d_in, const int* in_sizes, int n_in,
                              void* d_out, int out_size)
{
    const float* gs      = (const float*)d_in[0];
    const float* prev    = (const float*)d_in[1];
    const float* cur     = (const float*)d_in[2];
    const float* tgtn    = (const float*)d_in[3];
    const float* bos     = (const float*)d_in[4];
    const float* inp_w1  = (const float*)d_in[5];
    const float* inp_b1  = (const float*)d_in[6];
    const float* inp_w2  = (const float*)d_in[7];
    const float* inp_b2  = (const float*)d_in[8];
    const float* sa_qkv_w= (const float*)d_in[9];
    const float* sa_qkv_b= (const float*)d_in[10];
    const float* sa_out_w= (const float*)d_in[11];
    const float* sa_out_b= (const float*)d_in[12];
    const float* ca_qkv_w= (const float*)d_in[13];
    const float* ca_qkv_b= (const float*)d_in[14];
    const float* ca_out_w= (const float*)d_in[15];
    const float* ca_out_b= (const float*)d_in[16];
    const float* ln_w    = (const float*)d_in[17];
    const float* ln_b    = (const float*)d_in[18];
    const float* ff_w1   = (const float*)d_in[19];
    const float* ff_b1   = (const float*)d_in[20];
    const float* ff_w2   = (const float*)d_in[21];
    const float* ff_b2   = (const float*)d_in[22];
    const float* proj_w1 = (const float*)d_in[23];
    const float* proj_b1 = (const float*)d_in[24];
    const float* proj_w2 = (const float*)d_in[25];
    const float* proj_b2 = (const float*)d_in[26];
    const int*   basis   = (const int*)d_in[27];

    cudaFuncSetAttribute(mma_gemm_k<1,0,1>, cudaFuncAttributeMaxDynamicSharedMemorySize, SMEM_TB1);
    cudaFuncSetAttribute(mma_gemm_k<1,0,0>, cudaFuncAttributeMaxDynamicSharedMemorySize, SMEM_TB1);
    cudaFuncSetAttribute(mma_gemm_k<1,1,1>, cudaFuncAttributeMaxDynamicSharedMemorySize, SMEM_TB1);
    cudaFuncSetAttribute(mma_gemm_k<1,2,0>, cudaFuncAttributeMaxDynamicSharedMemorySize, SMEM_TB1);
    cudaFuncSetAttribute(mma_gemm_k<0,0,1>, cudaFuncAttributeMaxDynamicSharedMemorySize, SMEM_TB0);

    float *h, *x2;
    __half *h16, *mem16, *qkv16, *att16, *xh, *wh;
    cudaGetSymbolAddress((void**)&h,    d_h);
    cudaGetSymbolAddress((void**)&x2,   d_x2);
    cudaGetSymbolAddress((void**)&h16,  d_h16);
    cudaGetSymbolAddress((void**)&mem16,d_mem16);
    cudaGetSymbolAddress((void**)&qkv16,d_qkv16);
    cudaGetSymbolAddress((void**)&att16,d_att16);
    cudaGetSymbolAddress((void**)&xh,   d_xh);
    cudaGetSymbolAddress((void**)&wh,   d_wh);

    const int M = Bb * Ss;          // 8192
    const long zero = 0;

    build1_k<<<(M * HIDh) / 256, 256>>>(tgtn, bos, inp_w1, inp_b1, xh);

    {   // group 1: sa_qkv | sa_out | ca_qkv | ca_out -> wh[0 .. 25165824)
        long a = 3L*3072*1024/4, b2_ = a + 3L*1024*1024/4, c = b2_ + 3L*3072*1024/4,
             d = c + 3L*1024*1024/4;
        cvtg_k<<<(unsigned)((d + 255) / 256), 256>>>(sa_qkv_w, sa_out_w, ca_qkv_w, ca_out_w,
                                                     wh, a, b2_, c, d);
    }
    {   // group 2: ff_w1 | ff_w2 | inp_w2 | proj_w1 -> wh[25165824 ..)
        long a = 3L*2048*1024/4, b2_ = a + 3L*1024*2048/4, c = b2_ + 512L*512/4,
             d = c + 512L*1024/4;
        cvtg_k<<<(unsigned)((d + 255) / 256), 256>>>(ff_w1, ff_w2, inp_w2, proj_w1,
                                                     wh + W_FFW1, a, b2_, c, d);
    }

    hgemm(1, 0, 0, xh, wh + W_INPW2, inp_b2, x2, M, HIDh, HIDh, HIDh, HIDh, HIDh,
          zero, zero, zero, zero, zero, zero, 1, 1, 1.f, 0);
    build2_k<<<M, 256>>>(x2, gs, prev, cur, h, h16, mem16);

    const long sTok  = (long)Ss * 3072;
    const long sAttB = (long)NHh * Ss * Ss;
    const long sAttH = (long)Ss * Ss;
    const float iscale = 1.f / 16.f;         // 1/sqrt(hd)

    for (int l = 0; l < 3; l++) {
        // ===== self-attention =====
        hgemm(1, 0, 1, h16, wh + W_SAQKV + (long)l * 3 * Dd * Dd, sa_qkv_b + (long)l * 3 * Dd,
              qkv16, M, 3 * Dd, Dd, Dd, Dd, 3 * Dd, zero, zero, zero, zero, zero, zero, 1, 1, 1.f, 0);
        hgemm(1, 0, 1, qkv16, qkv16 + Dd, nullptr, att16, Ss, Ss, HDh, 3 * Dd, 3 * Dd, Ss,
              sTok, (long)HDh, sTok, (long)HDh, sAttB, sAttH, Bb, NHh, iscale, 1);
        softmax_k<<<dim3(Ss, Bb * NHh), 256>>>(att16, 1);
        hgemm(0, 0, 1, att16, qkv16 + 2 * Dd, nullptr, xh, Ss, HDh, Ss, Ss, 3 * Dd, Dd,
              sAttB, sAttH, sTok, (long)HDh, (long)Ss * Dd, (long)HDh, Bb, NHh, 1.f, 2);
        hgemm(1, 0, 0, xh, wh + W_SAOUT + (long)l * Dd * Dd, sa_out_b + (long)l * Dd, x2,
              M, Dd, Dd, Dd, Dd, Dd, zero, zero, zero, zero, zero, zero, 1, 1, 1.f, 0);
        ln_add_k<<<M, 256>>>(h, h16, x2, ln_w + (long)(l * 3 + 0) * Dd, ln_b + (long)(l * 3 + 0) * Dd);

        // ===== cross-attention =====
        hgemm(1, 0, 1, h16, wh + W_CAQKV + (long)l * 3 * Dd * Dd, ca_qkv_b + (long)l * 3 * Dd,
              qkv16, M, Dd, Dd, Dd, Dd, 3 * Dd, zero, zero, zero, zero, zero, zero, 1, 1, 1.f, 0);
        hgemm(1, 0, 1, mem16, wh + W_CAQKV + (long)l * 3 * Dd * Dd + (long)Dd * Dd,
              ca_qkv_b + (long)l * 3 * Dd + Dd, qkv16 + Dd,
              M, 2 * Dd, Dd, Dd, Dd, 3 * Dd, zero, zero, zero, zero, zero, zero, 1, 1, 1.f, 0);
        hgemm(1, 0, 1, qkv16, qkv16 + Dd, nullptr, att16, Ss, Ss, HDh, 3 * Dd, 3 * Dd, Ss,
              sTok, (long)HDh, sTok, (long)HDh, sAttB, sAttH, Bb, NHh, iscale, 0);
        softmax_k<<<dim3(Ss, Bb * NHh), 256>>>(att16, 0);
        hgemm(0, 0, 1, att16, qkv16 + 2 * Dd, nullptr, xh, Ss, HDh, Ss, Ss, 3 * Dd, Dd,
              sAttB, sAttH, sTok, (long)HDh, (long)Ss * Dd, (long)HDh, Bb, NHh, 1.f, 0);
        hgemm(1, 0, 0, xh, wh + W_CAOUT + (long)l * Dd * Dd, ca_out_b + (long)l * Dd, x2,
              M, Dd, Dd, Dd, Dd, Dd, zero, zero, zero, zero, zero, zero, 1, 1, 1.f, 0);
        ln_add_k<<<M, 256>>>(h, h16, x2, ln_w + (long)(l * 3 + 1) * Dd, ln_b + (long)(l * 3 + 1) * Dd);

        // ===== feed-forward =====
        hgemm(1, 1, 1, h16, wh + W_FFW1 + (long)l * DFFf * Dd, ff_b1 + (long)l * DFFf, xh,
              M, DFFf, Dd, Dd, Dd, DFFf, zero, zero, zero, zero, zero, zero, 1, 1, 1.f, 0);
        hgemm(1, 0, 0, xh, wh + W_FFW2 + (long)l * Dd * DFFf, ff_b2 + (long)l * Dd, x2,
              M, Dd, DFFf, DFFf, DFFf, Dd, zero, zero, zero, zero, zero, zero, 1, 1, 1.f, 0);
        ln_add_k<<<M, 256>>>(h, h16, x2, ln_w + (long)(l * 3 + 2) * Dd, ln_b + (long)(l * 3 + 2) * Dd);
    }

    // ---- output head ----
    hgemm(1, 2, 0, h16, wh + W_PROJW1, proj_b1, x2, M, HIDh, Dd, Dd, Dd, HIDh,
          zero, zero, zero, zero, zero, zero, 1, 1, 1.f, 0);
    final_k<<<(Bb * Ls + 7) / 8, 256>>>(x2, proj_w2, proj_b2, basis, (float*)d_out);
}

// round 17
// speedup vs baseline: 1.0349x; 1.0349x over previous
#include <cuda_runtime.h>
#include <cuda_fp16.h>
#include <math.h>
#include <stdint.h>

// ---------------- problem constants ----------------
#define Bb 16
#define Ls 511
#define Ss 512
#define Dd 1024
#define HIDh 512
#define DFFf 2048
#define EAe 256
#define NHh 4
#define HDh 256   // D/NH

// ---------------- GEMM tile config: CTA 128x128, warp 64x32, BK=32, 4 stages ----
#define AP 40                     // A smem pitch (halves)
#define BP1 40                    // B smem pitch, TB=1
#define BP0 136                   // B smem pitch, TB=0 (128 + 8 pad)
#define AE_H (128*AP)             // 5120 halves per A stage
#define STG1_H (AE_H + 128*BP1)   // 10240
#define STG0_H (AE_H + 32*BP0)    // 9472
#define SMEM_TB1 (STG1_H*2*4)     // 81920 B
#define SMEM_TB0 (STG0_H*2*4)     // 75776 B

// ---------------- scratch (static device memory) ----------------
__device__ float  d_h   [8192L*1024];
__device__ float  d_x2  [8192L*1024];
__device__ __half d_xd  [8192L*1024];
__device__ __half d_h16 [8192L*1024];
__device__ __half d_mem16[8192L*1024];
__device__ __half d_qkv16[8192L*3072];
__device__ __half d_att16[64L*512*512];
__device__ __half d_xh  [8192L*2048];
__device__ __half d_wh  [38535168];

// weight-region offsets in d_wh (halves) — contiguous pack
#define W_SAQKV  0L
#define W_SAOUT  9437184L
#define W_CAQKV  12582912L
#define W_CAOUT  22020096L
#define W_FFW1   25165824L
#define W_FFW2   31457280L
#define W_INPW2  37748736L
#define W_PROJW1 38010880L

// ---------------- asm helpers ----------------
__device__ __forceinline__ void cpa(uint32_t d, const __half* s) {
    asm volatile("cp.async.cg.shared.global [%0], [%1], 16;" :: "r"(d), "l"(s));
}
#define LDSM4(r0,r1,r2,r3,a) \
    asm volatile("ldmatrix.sync.aligned.m8n8.x4.shared.b16 {%0,%1,%2,%3}, [%4];" \
                 : "=r"(r0),"=r"(r1),"=r"(r2),"=r"(r3) : "r"(a))
#define LDSM4T(r0,r1,r2,r3,a) \
    asm volatile("ldmatrix.sync.aligned.m8n8.x4.trans.shared.b16 {%0,%1,%2,%3}, [%4];" \
                 : "=r"(r0),"=r"(r1),"=r"(r2),"=r"(r3) : "r"(a))

__device__ __forceinline__ void mma16(float* c, const uint32_t* a, const uint32_t* b) {
    asm volatile(
        "mma.sync.aligned.m16n8k16.row.col.f32.f16.f16.f32 "
        "{%0,%1,%2,%3}, {%4,%5,%6,%7}, {%8,%9}, {%0,%1,%2,%3};"
        : "+f"(c[0]), "+f"(c[1]), "+f"(c[2]), "+f"(c[3])
        : "r"(a[0]), "r"(a[1]), "r"(a[2]), "r"(a[3]), "r"(b[0]), "r"(b[1]));
}

// ---------------- fp16 tensor-core GEMM ----------------
// C = act(alpha * A @ op(B) + bias).  A [M,K] half row-major.
// TB=1: B [N,K]; TB=0: B [K,N]. OUTH=1: C half, else C float.
// CTA 128x128, 8 warps (2x4) of 64x32, BK=32, 4-stage cp.async, 2 CTAs/SM.
// cmode: 0 = dense; 1 = causal score GEMM (skip CTA tiles with n0>m0);
//        2 = causal P@V (K-loop truncated at m0+128; P upper triangle is zero).
template<int TB, int ACT, int OUTH>
__global__ void __launch_bounds__(256, 2)
mma_gemm_k(const __half* __restrict__ A, const __half* __restrict__ B,
           const float* __restrict__ bias, void* __restrict__ Cv,
           int K, int lda, int ldb, int ldc,
           long sAb, long sAh, long sBb, long sBh, long sCb, long sCh,
           int nh, float alpha, int cmode)
{
    constexpr int BP = TB ? BP1 : BP0;
    constexpr int STG_H = TB ? STG1_H : STG0_H;
    constexpr uint32_t STG_B = STG_H * 2;
    constexpr uint32_t AE_B = AE_H * 2;

    int m0 = blockIdx.y * 128, n0 = blockIdx.x * 128;
    if (cmode == 1 && n0 > m0) return;   // strictly-upper tile: P is zero there

    extern __shared__ __half smem[];
    uint32_t sb = (uint32_t)__cvta_generic_to_shared(smem);

    int tid = threadIdx.x;
    int wid = tid >> 5, lane = tid & 31;
    int gq = lane >> 2, gr = lane & 3;
    int wm0 = (wid >> 2) * 64;     // 2 warp rows
    int wn0 = (wid & 3) * 32;      // 4 warp cols

    int z = blockIdx.z, bb = z / nh, hh = z - bb * nh;
    A += bb * sAb + hh * sAh;
    B += bb * sBb + hh * sBh;

    float acc[4][4][4];
    #pragma unroll
    for (int i = 0; i < 4; i++)
        #pragma unroll
        for (int j = 0; j < 4; j++)
            #pragma unroll
            for (int q = 0; q < 4; q++) acc[i][j][q] = 0.f;

    auto ldst = [&](int s, int k0) {
        uint32_t base = sb + s * STG_B;
        // A: 128 rows x 32 halves = 512 16B-chunks
        #pragma unroll
        for (int i = 0; i < 2; i++) {
            int ch = tid + 256 * i;
            int c = ch >> 7, row = ch & 127;
            cpa(base + (uint32_t)(row * AP + c * 8) * 2,
                A + (long)(m0 + row) * lda + k0 + c * 8);
        }
        uint32_t bbase = base + AE_B;
        if (TB) {
            #pragma unroll
            for (int i = 0; i < 2; i++) {
                int ch = tid + 256 * i;
                int c = ch >> 7, row = ch & 127;
                cpa(bbase + (uint32_t)(row * BP + c * 8) * 2,
                    B + (long)(n0 + row) * ldb + k0 + c * 8);
            }
        } else {
            // B: 32 k-rows x 128 halves = 512 chunks
            #pragma unroll
            for (int i = 0; i < 2; i++) {
                int ch = tid + 256 * i;
                int row = ch >> 4, c = ch & 15;
                cpa(bbase + (uint32_t)(row * BP + c * 8) * 2,
                    B + (long)(k0 + row) * ldb + n0 + c * 8);
            }
        }
        asm volatile("cp.async.commit_group;" ::: "memory");
    };

    int nk = K / 32;
    if (cmode == 2) { int lim = (m0 >> 5) + 4; if (lim < nk) nk = lim; }

    ldst(0, 0); ldst(1, 32); ldst(2, 64);

    uint32_t a_lo = (uint32_t)((lane & 15) * AP + (lane >> 4) * 8) * 2;
    uint32_t b_lo = (uint32_t)((lane & 15) * BP + (lane >> 4) * 8) * 2;

    for (int it = 0; it < nk; it++) {
        asm volatile("cp.async.wait_group 2;" ::: "memory");
        __syncthreads();
        if (it + 3 < nk) ldst((it + 3) & 3, (it + 3) * 32);
        else asm volatile("cp.async.commit_group;" ::: "memory");

        uint32_t sbase = sb + (uint32_t)(it & 3) * STG_B;
        uint32_t aA = sbase + a_lo;
        uint32_t aB = sbase + AE_B + b_lo;

        #pragma unroll
        for (int kk = 0; kk < 2; kk++) {
            uint32_t afr[4][4];
            #pragma unroll
            for (int mi = 0; mi < 4; mi++)
                LDSM4(afr[mi][0], afr[mi][1], afr[mi][2], afr[mi][3],
                      aA + (uint32_t)((wm0 + mi * 16) * AP) * 2 + kk * 32);
            uint32_t bfr[4][2];
            #pragma unroll
            for (int nj = 0; nj < 2; nj++) {
                uint32_t r0, r1, r2, r3;
                if (TB) {
                    LDSM4(r0, r1, r2, r3,
                          aB + (uint32_t)((wn0 + nj * 16) * BP) * 2 + kk * 32);
                    bfr[2*nj][0] = r0; bfr[2*nj][1] = r2;
                    bfr[2*nj+1][0] = r1; bfr[2*nj+1][1] = r3;
                } else {
                    LDSM4T(r0, r1, r2, r3,
                           aB + (uint32_t)(kk * 16 * BP) * 2 + (uint32_t)(wn0 + nj * 16) * 2);
                    bfr[2*nj][0] = r0; bfr[2*nj][1] = r1;
                    bfr[2*nj+1][0] = r2; bfr[2*nj+1][1] = r3;
                }
            }
            #pragma unroll
            for (int mi = 0; mi < 4; mi++)
                #pragma unroll
                for (int ni = 0; ni < 4; ni++)
                    mma16(acc[mi][ni], afr[mi], bfr[ni]);
        }
    }

    // epilogue
    #pragma unroll
    for (int mi = 0; mi < 4; mi++) {
        int r0 = m0 + wm0 + mi * 16 + gq;
        #pragma unroll
        for (int ni = 0; ni < 4; ni++) {
            int c0 = n0 + wn0 + ni * 8 + gr * 2;
            float bz0 = 0.f, bz1 = 0.f;
            if (bias) { bz0 = bias[c0]; bz1 = bias[c0 + 1]; }
            #pragma unroll
            for (int hi = 0; hi < 2; hi++) {
                float x = acc[mi][ni][hi * 2 + 0] * alpha + bz0;
                float y = acc[mi][ni][hi * 2 + 1] * alpha + bz1;
                if (ACT == 1) { x = fmaxf(x, 0.f); y = fmaxf(y, 0.f); }
                if (ACT == 2) { x = (x >= 0.f) ? x : 0.01f * x; y = (y >= 0.f) ? y : 0.01f * y; }
                long off = (long)(r0 + hi * 8) * ldc + c0 + bb * sCb + hh * sCh;
                if (OUTH) {
                    *reinterpret_cast<__half2*>((__half*)Cv + off) = __floats2half2_rn(x, y);
                } else {
                    float2 v; v.x = x; v.y = y;
                    *reinterpret_cast<float2*>((float*)Cv + off) = v;
                }
            }
        }
    }
}

// ---------------- fused weight convert: 4 fp32 segments -> contiguous fp16 pack ----
__global__ void cvtg_k(const float* __restrict__ s0, const float* __restrict__ s1,
                       const float* __restrict__ s2, const float* __restrict__ s3,
                       __half* __restrict__ dst, long c0, long c1, long c2, long c3)
{
    long i = (long)blockIdx.x * 256 + threadIdx.x;
    if (i >= c3) return;
    const float* s;
    long base;
    if (i < c0)      { s = s0; base = 0; }
    else if (i < c1) { s = s1; base = c0; }
    else if (i < c2) { s = s2; base = c1; }
    else             { s = s3; base = c2; }
    float4 v = reinterpret_cast<const float4*>(s)[i - base];
    __half2* o = reinterpret_cast<__half2*>(dst + i * 4);
    o[0] = __floats2half2_rn(v.x, v.y);
    o[1] = __floats2half2_rn(v.z, v.w);
}

// ---------------- softmax: fp16 in-place (scores -> probabilities) ----------------
__global__ void softmax_k(__half* __restrict__ att, int causal)
{
    int q = blockIdx.x;
    int z = blockIdx.y;
    __half* p = att + ((long)z * Ss + q) * Ss;
    int len = causal ? (q + 1) : Ss;
    int tid = threadIdx.x;
    __shared__ float sh[8];

    float v0 = (tid < len) ? __half2float(p[tid]) : -1e30f;
    float v1 = (tid + 256 < len) ? __half2float(p[tid + 256]) : -1e30f;
    float mx = fmaxf(v0, v1);
    #pragma unroll
    for (int o2 = 16; o2; o2 >>= 1) mx = fmaxf(mx, __shfl_xor_sync(~0u, mx, o2));
    if ((tid & 31) == 0) sh[tid >> 5] = mx;
    __syncthreads();
    mx = sh[0];
    #pragma unroll
    for (int w = 1; w < 8; w++) mx = fmaxf(mx, sh[w]);

    float e0 = (tid < len) ? __expf(v0 - mx) : 0.f;
    float e1 = (tid + 256 < len) ? __expf(v1 - mx) : 0.f;
    float s = e0 + e1;
    #pragma unroll
    for (int o2 = 16; o2; o2 >>= 1) s += __shfl_xor_sync(~0u, s, o2);
    __syncthreads();
    if ((tid & 31) == 0) sh[tid >> 5] = s;
    __syncthreads();
    s = 0.f;
    #pragma unroll
    for (int w = 0; w < 8; w++) s += sh[w];
    float inv = 1.f / s;

    p[tid]       = __float2half_rn(e0 * inv);
    p[tid + 256] = __float2half_rn(e1 * inv);
}

// ---------------- h = LN(h + delta16); also write h16 ----------------
__global__ void ln_add_k(float* __restrict__ h, __half* __restrict__ h16,
                         const __half* __restrict__ d,
                         const float* __restrict__ w, const float* __restrict__ b)
{
    long row = blockIdx.x;
    float* x = h + row * Dd;
    __half* x16 = h16 + row * Dd;
    const __half* dd = d + row * Dd;
    int tid = threadIdx.x;
    __shared__ float sh[256];

    float v[4];
    float s = 0.f;
    #pragma unroll
    for (int t = 0; t < 4; t++) {
        int i = tid + t * 256;
        v[t] = x[i] + __half2float(dd[i]);
        s += v[t];
    }
    sh[tid] = s; __syncthreads();
    for (int st = 128; st > 0; st >>= 1) { if (tid < st) sh[tid] += sh[tid + st]; __syncthreads(); }
    float mean = sh[0] * (1.f / Dd); __syncthreads();

    float s2 = 0.f;
    #pragma unroll
    for (int t = 0; t < 4; t++) { float u = v[t] - mean; s2 += u * u; }
    sh[tid] = s2; __syncthreads();
    for (int st = 128; st > 0; st >>= 1) { if (tid < st) sh[tid] += sh[tid + st]; __syncthreads(); }
    float rstd = rsqrtf(sh[0] * (1.f / Dd) + 1e-5f);

    #pragma unroll
    for (int t = 0; t < 4; t++) {
        int i = tid + t * 256;
        float r = (v[t] - mean) * rstd * w[i] + b[i];
        x[i] = r;
        x16[i] = __float2half_rn(r);
    }
}

// ---------------- input projection stage 1 (half out) ----------------
__global__ void build1_k(const float* __restrict__ tgtn, const float* __restrict__ bos,
                         const float* __restrict__ w1, const float* __restrict__ b1,
                         __half* __restrict__ out)
{
    long idx = (long)blockIdx.x * 256 + threadIdx.x;
    long row = idx >> 9;
    int j = (int)(idx & 511);
    int bb = (int)(row >> 9);
    int s = (int)(row & 511);
    float t = (s == 0) ? bos[0] : tgtn[bb * Ls + s - 1];
    float v = t * w1[j] + b1[j];
    out[idx] = __float2half_rn((v >= 0.f) ? v : 0.01f * v);
}

// ---------------- assemble tgt(+PE) -> h,h16 and mem16 ----------------
__global__ void build2_k(const float* __restrict__ x2, const float* __restrict__ gs,
                         const float* __restrict__ prev, const float* __restrict__ cur,
                         float* __restrict__ h, __half* __restrict__ h16,
                         __half* __restrict__ mem16)
{
    int row = blockIdx.x;
    int bb = row >> 9;
    int s = row & 511;
    long ob = (long)row * Dd;
    for (int i = threadIdx.x; i < Dd; i += 256) {
        float tv, mv;
        if (i < HIDh) {
            int jj = i & ~1;
            float div = __expf((float)jj * (-9.210340371976184f / 512.f));
            double ang = (double)s * (double)div;
            double r = ang - 6.283185307179586 * rint(ang * 0.15915494309189535);
            float fr = (float)r;
            float pe = (i & 1) ? cosf(fr) : sinf(fr);
            tv = x2[(long)row * HIDh + i] + pe;
            mv = gs[(long)row * HIDh + i];
        } else if (i < HIDh + EAe) {
            float a = prev[bb * EAe + (i - HIDh)];
            tv = a; mv = a;
        } else {
            float a = cur[bb * EAe + (i - HIDh - EAe)];
            tv = a; mv = a;
        }
        h[ob + i] = tv;
        h16[ob + i] = __float2half_rn(tv);
        mem16[ob + i] = __float2half_rn(mv);
    }
}

// ---------------- final: y2 = y1 @ w2^T + b2, masked ----------------
__global__ void final_k(const float* __restrict__ y1, const float* __restrict__ w2,
                        const float* __restrict__ b2, const int* __restrict__ basis,
                        float* __restrict__ out)
{
    int idx = blockIdx.x * 8 + (threadIdx.x >> 5);
    if (idx >= Bb * Ls) return;
    int bb = idx / Ls, l = idx % Ls;
    const float* r = y1 + ((long)bb * Ss + l + 1) * HIDh;
    int lane = threadIdx.x & 31;
    float s = 0.f;
    for (int j = lane; j < HIDh; j += 32) s += r[j] * w2[j];
    #pragma unroll
    for (int o = 16; o; o >>= 1) s += __shfl_xor_sync(0xffffffffu, s, o);
    if (lane == 0) out[idx] = (l < basis[bb]) ? (s + b2[0]) : 0.f;
}

// ---------------- host-side launcher ----------------
static void hgemm(int TB, int ACT, int OUTH,
                  const __half* A, const __half* B, const float* bias, void* C,
                  int M, int N, int K, int lda, int ldb, int ldc,
                  long sAb, long sAh, long sBb, long sBh, long sCb, long sCh,
                  int nb, int nh, float alpha, int cmode)
{
    dim3 grid(N / 128, M / 128, nb * nh);
#define HCALL(tb, act, oh, sm) mma_gemm_k<tb, act, oh><<<grid, 256, sm>>>( \
        A, B, bias, C, K, lda, ldb, ldc, sAb, sAh, sBb, sBh, sCb, sCh, nh, alpha, cmode)
    if (TB == 1 && ACT == 0 && OUTH == 1) HCALL(1, 0, 1, SMEM_TB1);
    else if (TB == 1 && ACT == 0 && OUTH == 0) HCALL(1, 0, 0, SMEM_TB1);
    else if (TB == 1 && ACT == 1 && OUTH == 1) HCALL(1, 1, 1, SMEM_TB1);
    else if (TB == 1 && ACT == 2 && OUTH == 0) HCALL(1, 2, 0, SMEM_TB1);
    else HCALL(0, 0, 1, SMEM_TB0);
#undef HCALL
}

extern "C" void kernel_launch(void* const* d_in, const int* in_sizes, int n_in,
                              void* d_out, int out_size)
{
    const float* gs      = (const float*)d_in[0];
    const float* prev    = (const float*)d_in[1];
    const float* cur     = (const float*)d_in[2];
    const float* tgtn    = (const float*)d_in[3];
    const float* bos     = (const float*)d_in[4];
    const float* inp_w1  = (const float*)d_in[5];
    const float* inp_b1  = (const float*)d_in[6];
    const float* inp_w2  = (const float*)d_in[7];
    const float* inp_b2  = (const float*)d_in[8];
    const float* sa_qkv_w= (const float*)d_in[9];
    const float* sa_qkv_b= (const float*)d_in[10];
    const float* sa_out_w= (const float*)d_in[11];
    const float* sa_out_b= (const float*)d_in[12];
    const float* ca_qkv_w= (const float*)d_in[13];
    const float* ca_qkv_b= (const float*)d_in[14];
    const float* ca_out_w= (const float*)d_in[15];
    const float* ca_out_b= (const float*)d_in[16];
    const float* ln_w    = (const float*)d_in[17];
    const float* ln_b    = (const float*)d_in[18];
    const float* ff_w1   = (const float*)d_in[19];
    const float* ff_b1   = (const float*)d_in[20];
    const float* ff_w2   = (const float*)d_in[21];
    const float* ff_b2   = (const float*)d_in[22];
    const float* proj_w1 = (const float*)d_in[23];
    const float* proj_b1 = (const float*)d_in[24];
    const float* proj_w2 = (const float*)d_in[25];
    const float* proj_b2 = (const float*)d_in[26];
    const int*   basis   = (const int*)d_in[27];

    cudaFuncSetAttribute(mma_gemm_k<1,0,1>, cudaFuncAttributeMaxDynamicSharedMemorySize, SMEM_TB1);
    cudaFuncSetAttribute(mma_gemm_k<1,0,0>, cudaFuncAttributeMaxDynamicSharedMemorySize, SMEM_TB1);
    cudaFuncSetAttribute(mma_gemm_k<1,1,1>, cudaFuncAttributeMaxDynamicSharedMemorySize, SMEM_TB1);
    cudaFuncSetAttribute(mma_gemm_k<1,2,0>, cudaFuncAttributeMaxDynamicSharedMemorySize, SMEM_TB1);
    cudaFuncSetAttribute(mma_gemm_k<0,0,1>, cudaFuncAttributeMaxDynamicSharedMemorySize, SMEM_TB0);

    float *h, *x2;
    __half *xd, *h16, *mem16, *qkv16, *att16, *xh, *wh;
    cudaGetSymbolAddress((void**)&h,    d_h);
    cudaGetSymbolAddress((void**)&x2,   d_x2);
    cudaGetSymbolAddress((void**)&xd,   d_xd);
    cudaGetSymbolAddress((void**)&h16,  d_h16);
    cudaGetSymbolAddress((void**)&mem16,d_mem16);
    cudaGetSymbolAddress((void**)&qkv16,d_qkv16);
    cudaGetSymbolAddress((void**)&att16,d_att16);
    cudaGetSymbolAddress((void**)&xh,   d_xh);
    cudaGetSymbolAddress((void**)&wh,   d_wh);

    const int M = Bb * Ss;          // 8192
    const long zero = 0;

    build1_k<<<(M * HIDh) / 256, 256>>>(tgtn, bos, inp_w1, inp_b1, xh);

    {   // group 1: sa_qkv | sa_out | ca_qkv | ca_out -> wh[0 .. 25165824)
        long a = 3L*3072*1024/4, b2_ = a + 3L*1024*1024/4, c = b2_ + 3L*3072*1024/4,
             d = c + 3L*1024*1024/4;
        cvtg_k<<<(unsigned)((d + 255) / 256), 256>>>(sa_qkv_w, sa_out_w, ca_qkv_w, ca_out_w,
                                                     wh, a, b2_, c, d);
    }
    {   // group 2: ff_w1 | ff_w2 | inp_w2 | proj_w1 -> wh[25165824 ..)
        long a = 3L*2048*1024/4, b2_ = a + 3L*1024*2048/4, c = b2_ + 512L*512/4,
             d = c + 512L*1024/4;
        cvtg_k<<<(unsigned)((d + 255) / 256), 256>>>(ff_w1, ff_w2, inp_w2, proj_w1,
                                                     wh + W_FFW1, a, b2_, c, d);
    }

    hgemm(1, 0, 0, xh, wh + W_INPW2, inp_b2, x2, M, HIDh, HIDh, HIDh, HIDh, HIDh,
          zero, zero, zero, zero, zero, zero, 1, 1, 1.f, 0);
    build2_k<<<M, 256>>>(x2, gs, prev, cur, h, h16, mem16);

    const long sTok  = (long)Ss * 3072;
    const long sAttB = (long)NHh * Ss * Ss;
    const long sAttH = (long)Ss * Ss;
    const float iscale = 1.f / 16.f;         // 1/sqrt(hd)

    for (int l = 0; l < 3; l++) {
        // ===== self-attention =====
        hgemm(1, 0, 1, h16, wh + W_SAQKV + (long)l * 3 * Dd * Dd, sa_qkv_b + (long)l * 3 * Dd,
              qkv16, M, 3 * Dd, Dd, Dd, Dd, 3 * Dd, zero, zero, zero, zero, zero, zero, 1, 1, 1.f, 0);
        hgemm(1, 0, 1, qkv16, qkv16 + Dd, nullptr, att16, Ss, Ss, HDh, 3 * Dd, 3 * Dd, Ss,
              sTok, (long)HDh, sTok, (long)HDh, sAttB, sAttH, Bb, NHh, iscale, 1);
        softmax_k<<<dim3(Ss, Bb * NHh), 256>>>(att16, 1);
        hgemm(0, 0, 1, att16, qkv16 + 2 * Dd, nullptr, xh, Ss, HDh, Ss, Ss, 3 * Dd, Dd,
              sAttB, sAttH, sTok, (long)HDh, (long)Ss * Dd, (long)HDh, Bb, NHh, 1.f, 2);
        hgemm(1, 0, 1, xh, wh + W_SAOUT + (long)l * Dd * Dd, sa_out_b + (long)l * Dd, xd,
              M, Dd, Dd, Dd, Dd, Dd, zero, zero, zero, zero, zero, zero, 1, 1, 1.f, 0);
        ln_add_k<<<M, 256>>>(h, h16, xd, ln_w + (long)(l * 3 + 0) * Dd, ln_b + (long)(l * 3 + 0) * Dd);

        // ===== cross-attention =====
        hgemm(1, 0, 1, h16, wh + W_CAQKV + (long)l * 3 * Dd * Dd, ca_qkv_b + (long)l * 3 * Dd,
              qkv16, M, Dd, Dd, Dd, Dd, 3 * Dd, zero, zero, zero, zero, zero, zero, 1, 1, 1.f, 0);
        hgemm(1, 0, 1, mem16, wh + W_CAQKV + (long)l * 3 * Dd * Dd + (long)Dd * Dd,
              ca_qkv_b + (long)l * 3 * Dd + Dd, qkv16 + Dd,
              M, 2 * Dd, Dd, Dd, Dd, 3 * Dd, zero, zero, zero, zero, zero, zero, 1, 1, 1.f, 0);
        hgemm(1, 0, 1, qkv16, qkv16 + Dd, nullptr, att16, Ss, Ss, HDh, 3 * Dd, 3 * Dd, Ss,
              sTok, (long)HDh, sTok, (long)HDh, sAttB, sAttH, Bb, NHh, iscale, 0);
        softmax_k<<<dim3(Ss, Bb * NHh), 256>>>(att16, 0);
        hgemm(0, 0, 1, att16, qkv16 + 2 * Dd, nullptr, xh, Ss, HDh, Ss, Ss, 3 * Dd, Dd,
              sAttB, sAttH, sTok, (long)HDh, (long)Ss * Dd, (long)HDh, Bb, NHh, 1.f, 0);
        hgemm(1, 0, 1, xh, wh + W_CAOUT + (long)l * Dd * Dd, ca_out_b + (long)l * Dd, xd,
              M, Dd, Dd, Dd, Dd, Dd, zero, zero, zero, zero, zero, zero, 1, 1, 1.f, 0);
        ln_add_k<<<M, 256>>>(h, h16, xd, ln_w + (long)(l * 3 + 1) * Dd, ln_b + (long)(l * 3 + 1) * Dd);

        // ===== feed-forward =====
        hgemm(1, 1, 1, h16, wh + W_FFW1 + (long)l * DFFf * Dd, ff_b1 + (long)l * DFFf, xh,
              M, DFFf, Dd, Dd, Dd, DFFf, zero, zero, zero, zero, zero, zero, 1, 1, 1.f, 0);
        hgemm(1, 0, 1, xh, wh + W_FFW2 + (long)l * Dd * DFFf, ff_b2 + (long)l * Dd, xd,
              M, Dd, DFFf, DFFf, DFFf, Dd, zero, zero, zero, zero, zero, zero, 1, 1, 1.f, 0);
        ln_add_k<<<M, 256>>>(h, h16, xd, ln_w + (long)(l * 3 + 2) * Dd, ln_b + (long)(l * 3 + 2) * Dd);
    }

    // ---- output head ----
    hgemm(1, 2, 0, h16, wh + W_PROJW1, proj_b1, x2, M, HIDh, Dd, Dd, Dd, HIDh,
          zero, zero, zero, zero, zero, zero, 1, 1, 1.f, 0);
    final_k<<<(Bb * Ls + 7) / 8, 256>>>(x2, proj_w2, proj_b2, basis, (float*)d_out);
}